// round 6
// baseline (speedup 1.0000x reference)
#include <cuda_runtime.h>
#include <math.h>

#define NB    2048
#define HID   64
#define TAU   22
#define K2B   8                 // batches per block in kernel 2

__device__ __align__(16) float g_Wv[NB * 2 * HID];   // [batch][graph][k] : 1 MB scratch

__device__ __forceinline__ float eluf(float x) { return x > 0.0f ? x : (__expf(x) - 1.0f); }

// ---------------- Kernel 1 : per-graph GAT collapse -> Wv ----------------
// one warp per (batch, graph); no block-wide synchronization at all.
__global__ void __launch_bounds__(128) k1_gat(
    const float* __restrict__ fp,
    const float* __restrict__ uW1, const float* __restrict__ uA,
    const float* __restrict__ dW1, const float* __restrict__ dA)
{
    __shared__ __align__(16) float feat[4][1280];   // 20 KB

    const int tid  = threadIdx.x;
    const int w    = tid >> 5;
    const int lane = tid & 31;
    const int unit = blockIdx.x * 4 + w;     // 0..4095
    const int b    = unit >> 1;
    const int g    = unit & 1;

    // 1) issue all feature loads (coalesced float4, 1 wavefront each)
    const float4* src = (const float4*)(fp + (long long)b * 2560 + g * 1280);
    float4 v[10];
    #pragma unroll
    for (int i = 0; i < 10; i++) v[i] = src[i * 32 + lane];

    // 2) while loads are in flight: per-warp C1/C2 from L1-hot globals
    const float* W1 = g ? dW1 : uW1;
    const float* A  = g ? dA  : uA;
    const float a0v = __ldg(&A[lane]),       a1v = __ldg(&A[lane + 32]);
    const float a2v = __ldg(&A[64 + lane]),  a3v = __ldg(&A[96 + lane]);
    float C1[7], C2[7];
    #pragma unroll
    for (int f = 0; f < 7; f++) {
        float w1a = __ldg(&W1[f * HID + lane]);
        float w1b = __ldg(&W1[f * HID + lane + 32]);
        float p1 = w1a * a0v + w1b * a1v;
        float p2 = w1a * a2v + w1b * a3v;
        #pragma unroll
        for (int o = 16; o; o >>= 1) {
            p1 += __shfl_xor_sync(0xffffffffu, p1, o);
            p2 += __shfl_xor_sync(0xffffffffu, p2, o);
        }
        C1[f] = p1; C2[f] = p2;
    }

    // 3) stage features to this warp's smem slab
    {
        float4* dst = (float4*)feat[w];
        #pragma unroll
        for (int i = 0; i < 10; i++) dst[i * 32 + lane] = v[i];
    }
    __syncwarp();

    // 4) read owned nodes {lane, lane+32, lane+64, lane+96}
    float x[4][7];
    #pragma unroll
    for (int n = 0; n < 4; n++) {
        const float* r = &feat[w][(n * 32 + lane) * 10];
        float2 p0 = *(const float2*)(r);
        float2 p1 = *(const float2*)(r + 2);
        float2 p2 = *(const float2*)(r + 4);
        x[n][0] = p0.x; x[n][1] = p0.y;
        x[n][2] = p1.x; x[n][3] = p1.y;
        x[n][4] = p2.x; x[n][5] = p2.y;
        x[n][6] = r[6];
    }

    // 5) logits: e_j = lrelu(s0 + x_j.C2); s0 from lane 0 (node 0)
    float s0l = 0.0f;
    #pragma unroll
    for (int f = 0; f < 7; f++) s0l = fmaf(x[0][f], C1[f], s0l);
    const float s0 = __shfl_sync(0xffffffffu, s0l, 0);

    float e[4];
    #pragma unroll
    for (int n = 0; n < 4; n++) {
        float t = 0.0f;
        #pragma unroll
        for (int f = 0; f < 7; f++) t = fmaf(x[n][f], C2[f], t);
        float vv = s0 + t;
        e[n] = vv > 0.0f ? vv : 0.2f * vv;
    }
    if (lane == 0) e[0] = -1e30f;

    // 6) softmax over 128 logits
    float m = fmaxf(fmaxf(e[0], e[1]), fmaxf(e[2], e[3]));
    #pragma unroll
    for (int o = 16; o; o >>= 1) m = fmaxf(m, __shfl_xor_sync(0xffffffffu, m, o));
    float p[4], z = 0.0f;
    #pragma unroll
    for (int n = 0; n < 4; n++) { p[n] = __expf(e[n] - m); z += p[n]; }
    #pragma unroll
    for (int o = 16; o; o >>= 1) z += __shfl_xor_sync(0xffffffffu, z, o);
    const float zi = 1.0f / z;

    // 7) Y = sum alpha_j x_j ; x0 broadcast
    float Y[7];
    #pragma unroll
    for (int f = 0; f < 7; f++) {
        float vv = p[0] * x[0][f] + p[1] * x[1][f] + p[2] * x[2][f] + p[3] * x[3][f];
        #pragma unroll
        for (int o = 16; o; o >>= 1) vv += __shfl_xor_sync(0xffffffffu, vv, o);
        Y[f] = vv * zi;
    }
    float x0[7];
    #pragma unroll
    for (int f = 0; f < 7; f++) x0[f] = __shfl_sync(0xffffffffu, x[0][f], 0);

    // 8) Wv[k] = elu(x0.W1[:,k]) + 127 * elu(Y.W1[:,k]) ; W1 L1-hot
    #pragma unroll
    for (int r = 0; r < 2; r++) {
        int k = lane + 32 * r;
        float c = 0.0f, l = 0.0f;
        #pragma unroll
        for (int f = 0; f < 7; f++) {
            float w1 = __ldg(&W1[f * HID + k]);
            c = fmaf(Y[f],  w1, c);
            l = fmaf(x0[f], w1, l);
        }
        g_Wv[unit * HID + k] = eluf(l) + 127.0f * eluf(c);
    }
}

// ---------------- Kernel 2 : G = Wv_u @ uW2 + Wv_d @ dW2 ; out = head(G) ---
__global__ void __launch_bounds__(256) k2_head(
    const float* __restrict__ uW2, const float* __restrict__ dW2,
    const float* __restrict__ fc2W, const float* __restrict__ fc2b,
    float* __restrict__ out)
{
    __shared__ __align__(16) float W2s[2][HID][HID];     // 32 KB
    __shared__ __align__(16) float F2s[HID][TAU];        // 5.5 KB
    __shared__ float fbs[TAU];
    __shared__ __align__(16) float Wvt[K2B][2][HID];     // 4 KB
    __shared__ __align__(16) float Gs[K2B][HID];         // 2 KB

    const int tid = threadIdx.x;

    {   // stage weights + Wv tile
        const float4* su = (const float4*)uW2;
        const float4* sd = (const float4*)dW2;
        float4* dw = (float4*)W2s;
        #pragma unroll
        for (int i = tid; i < 1024; i += 256) {
            dw[i]        = su[i];
            dw[1024 + i] = sd[i];
        }
        for (int i = tid; i < HID * TAU; i += 256) ((float*)F2s)[i] = fc2W[i];
        if (tid < TAU) fbs[tid] = fc2b[tid];
        const float4* wv = (const float4*)(g_Wv + blockIdx.x * K2B * 2 * HID);
        ((float4*)Wvt)[tid] = wv[tid];     // 256 float4 = 1024 floats
    }
    __syncthreads();

    // each thread: output column m for batches bb and bb+4
    {
        const int m  = tid & 63;
        const int b0 = tid >> 6;
        #pragma unroll
        for (int r = 0; r < 2; r++) {
            const int bb = b0 + 4 * r;
            float au = 0.0f, ad = 0.0f;
            #pragma unroll 8
            for (int k = 0; k < HID; k++) {
                au = fmaf(W2s[0][k][m], Wvt[bb][0][k], au);
                ad = fmaf(W2s[1][k][m], Wvt[bb][1][k], ad);
            }
            Gs[bb][m] = au + ad;
        }
    }
    __syncthreads();

    if (tid < K2B * TAU) {
        const int b2 = tid / TAU, t = tid - b2 * TAU;
        float acc = fbs[t];
        #pragma unroll 8
        for (int mm = 0; mm < HID; mm++)
            acc = fmaf(Gs[b2][mm], F2s[mm][t], acc);
        acc = fminf(fmaxf(acc, 0.0f), 10.0f);
        out[((long long)blockIdx.x * K2B + b2) * TAU + t] = acc;
    }
}

extern "C" void kernel_launch(void* const* d_in, const int* in_sizes, int n_in,
                              void* d_out, int out_size)
{
    const float* fp    = (const float*)d_in[0];
    const float* uW1   = (const float*)d_in[1];
    const float* uA    = (const float*)d_in[2];
    const float* uW2   = (const float*)d_in[3];
    // d_in[4] = u_out_a : provably unused (singleton/uniform layer-2 softmax)
    const float* dW1   = (const float*)d_in[5];
    const float* dA    = (const float*)d_in[6];
    const float* dW2   = (const float*)d_in[7];
    // d_in[8] = d_out_a : unused
    const float* fc2W  = (const float*)d_in[9];
    const float* fc2b  = (const float*)d_in[10];
    float* out = (float*)d_out;

    k1_gat<<<NB * 2 / 4, 128>>>(fp, uW1, uA, dW1, dA);
    k2_head<<<NB / K2B, 256>>>(uW2, dW2, fc2W, fc2b, out);
}

// round 7
// speedup vs baseline: 1.1858x; 1.1858x over previous
#include <cuda_runtime.h>
#include <math.h>

#define NB    2048
#define HID   64
#define TAU   22

__device__ __forceinline__ float eluf(float x) { return x > 0.0f ? x : (__expf(x) - 1.0f); }

// One warp per (batch, graph); 4 warps / block = 2 batches / block.
// Hot path has zero block barriers; one __syncthreads before the tiny head.
__global__ void __launch_bounds__(128) gat_fused(
    const float* __restrict__ fp,
    const float* __restrict__ uW1, const float* __restrict__ uA,
    const float* __restrict__ uW2,
    const float* __restrict__ dW1, const float* __restrict__ dA,
    const float* __restrict__ dW2,
    const float* __restrict__ fc2W, const float* __restrict__ fc2b,
    float* __restrict__ out)
{
    __shared__ __align__(16) float feat[4][1280];   // 20 KB : per-warp graph
    __shared__ float Wvs[4][HID];                   // per-warp h1 vector
    __shared__ float Gp[4][HID];                    // per-warp W2 output

    const int tid  = threadIdx.x;
    const int w    = tid >> 5;
    const int lane = tid & 31;
    const int unit = blockIdx.x * 4 + w;   // 0..4095
    const int b    = unit >> 1;            // batch
    const int g    = unit & 1;             // 0 = up, 1 = down

    // 1) issue all feature loads (coalesced float4, 1 wavefront each)
    const float4* src = (const float4*)(fp + (long long)b * 2560 + g * 1280);
    float4 v[10];
    #pragma unroll
    for (int i = 0; i < 10; i++) v[i] = src[i * 32 + lane];

    // 2) overlap with loads: per-warp C1/C2 = W1 @ a halves (L1-hot globals)
    const float* W1 = g ? dW1 : uW1;
    const float* A  = g ? dA  : uA;
    const float a0v = __ldg(&A[lane]),      a1v = __ldg(&A[lane + 32]);
    const float a2v = __ldg(&A[64 + lane]), a3v = __ldg(&A[96 + lane]);
    float C1[7], C2[7];
    #pragma unroll
    for (int f = 0; f < 7; f++) {
        float w1a = __ldg(&W1[f * HID + lane]);
        float w1b = __ldg(&W1[f * HID + lane + 32]);
        float p1 = w1a * a0v + w1b * a1v;
        float p2 = w1a * a2v + w1b * a3v;
        #pragma unroll
        for (int o = 16; o; o >>= 1) {
            p1 += __shfl_xor_sync(0xffffffffu, p1, o);
            p2 += __shfl_xor_sync(0xffffffffu, p2, o);
        }
        C1[f] = p1; C2[f] = p2;
    }

    // 3) stage features into this warp's smem slab
    {
        float4* dst = (float4*)feat[w];
        #pragma unroll
        for (int i = 0; i < 10; i++) dst[i * 32 + lane] = v[i];
    }
    __syncwarp();

    // 4) read owned nodes {lane, lane+32, lane+64, lane+96}
    float x[4][7];
    #pragma unroll
    for (int n = 0; n < 4; n++) {
        const float* r = &feat[w][(n * 32 + lane) * 10];
        float2 p0 = *(const float2*)(r);
        float2 p1 = *(const float2*)(r + 2);
        float2 p2 = *(const float2*)(r + 4);
        x[n][0] = p0.x; x[n][1] = p0.y;
        x[n][2] = p1.x; x[n][3] = p1.y;
        x[n][4] = p2.x; x[n][5] = p2.y;
        x[n][6] = r[6];
    }

    // 5) logits e_j = lrelu(s0 + x_j.C2); s0 from lane 0 (node 0)
    float s0l = 0.0f;
    #pragma unroll
    for (int f = 0; f < 7; f++) s0l = fmaf(x[0][f], C1[f], s0l);
    const float s0 = __shfl_sync(0xffffffffu, s0l, 0);

    float e[4];
    #pragma unroll
    for (int n = 0; n < 4; n++) {
        float t = 0.0f;
        #pragma unroll
        for (int f = 0; f < 7; f++) t = fmaf(x[n][f], C2[f], t);
        float vv = s0 + t;
        e[n] = vv > 0.0f ? vv : 0.2f * vv;
    }
    if (lane == 0) e[0] = -1e30f;          // mask center

    // 6) softmax over 128 logits
    float m = fmaxf(fmaxf(e[0], e[1]), fmaxf(e[2], e[3]));
    #pragma unroll
    for (int o = 16; o; o >>= 1) m = fmaxf(m, __shfl_xor_sync(0xffffffffu, m, o));
    float p[4], z = 0.0f;
    #pragma unroll
    for (int n = 0; n < 4; n++) { p[n] = __expf(e[n] - m); z += p[n]; }
    #pragma unroll
    for (int o = 16; o; o >>= 1) z += __shfl_xor_sync(0xffffffffu, z, o);
    const float zi = 1.0f / z;

    // 7) Y = sum alpha_j x_j ; x0 broadcast from lane 0
    float Y[7];
    #pragma unroll
    for (int f = 0; f < 7; f++) {
        float vv = p[0] * x[0][f] + p[1] * x[1][f] + p[2] * x[2][f] + p[3] * x[3][f];
        #pragma unroll
        for (int o = 16; o; o >>= 1) vv += __shfl_xor_sync(0xffffffffu, vv, o);
        Y[f] = vv * zi;
    }
    float x0[7];
    #pragma unroll
    for (int f = 0; f < 7; f++) x0[f] = __shfl_sync(0xffffffffu, x[0][f], 0);

    // 8) Wv[k] = elu(x0.W1[:,k]) + 127*elu(Y.W1[:,k]) -> smem strip
    #pragma unroll
    for (int r = 0; r < 2; r++) {
        int k = lane + 32 * r;
        float c = 0.0f, l = 0.0f;
        #pragma unroll
        for (int f = 0; f < 7; f++) {
            float w1 = __ldg(&W1[f * HID + k]);
            c = fmaf(Y[f],  w1, c);
            l = fmaf(x0[f], w1, l);
        }
        Wvs[w][k] = eluf(l) + 127.0f * eluf(c);
    }
    __syncwarp();

    // 9) per-warp W2 matvec: Gp[w][m] = sum_k W2[k][m] * Wv[k]
    {
        const float* W2 = g ? dW2 : uW2;
        float g0 = 0.0f, g1 = 0.0f;
        #pragma unroll 8
        for (int k = 0; k < HID; k++) {
            float wvk = Wvs[w][k];                    // LDS broadcast
            g0 = fmaf(__ldg(&W2[k * HID + lane]),      wvk, g0);
            g1 = fmaf(__ldg(&W2[k * HID + lane + 32]), wvk, g1);
        }
        Gp[w][lane]      = g0;
        Gp[w][lane + 32] = g1;
    }
    __syncthreads();

    // 10) head: out = clip(relu((Gu+Gd) @ fc2W + b), 0, 10)   (2 batches x 22)
    if (tid < 2 * TAU) {
        const int bb = tid / TAU, t = tid - bb * TAU;
        float acc = __ldg(&fc2b[t]);
        #pragma unroll 8
        for (int mm = 0; mm < HID; mm++)
            acc = fmaf(Gp[2 * bb][mm] + Gp[2 * bb + 1][mm],
                       __ldg(&fc2W[mm * TAU + t]), acc);
        acc = fminf(fmaxf(acc, 0.0f), 10.0f);
        out[((long long)blockIdx.x * 2 + bb) * TAU + t] = acc;
    }
}

extern "C" void kernel_launch(void* const* d_in, const int* in_sizes, int n_in,
                              void* d_out, int out_size)
{
    const float* fp    = (const float*)d_in[0];
    const float* uW1   = (const float*)d_in[1];
    const float* uA    = (const float*)d_in[2];
    const float* uW2   = (const float*)d_in[3];
    // d_in[4] = u_out_a : provably unused (singleton/uniform layer-2 softmax)
    const float* dW1   = (const float*)d_in[5];
    const float* dA    = (const float*)d_in[6];
    const float* dW2   = (const float*)d_in[7];
    // d_in[8] = d_out_a : unused
    const float* fc2W  = (const float*)d_in[9];
    const float* fc2b  = (const float*)d_in[10];
    float* out = (float*)d_out;

    gat_fused<<<NB / 2, 128>>>(fp, uW1, uA, uW2, dW1, dA, dW2, fc2W, fc2b, out);
}